// round 16
// baseline (speedup 1.0000x reference)
#include <cuda_runtime.h>

#define BATCH 256
#define SEQ   512
#define DIM   7
#define THREADS 128
#define RPT     2            // rows per thread (phase A)
#define ROWS_CTA 128         // rows covered per CTA (quarter batch)
#define NPAIR (SEQ / 2)      // 256 t-pairs

typedef unsigned long long u64;

// ---------- packed f32x2 helpers (Blackwell-only, PTX required) ----------
__device__ __forceinline__ u64 pk2(float a, float b) {
    u64 r;
    asm("mov.b64 %0, {%1, %2};" : "=l"(r) : "f"(a), "f"(b));
    return r;
}
__device__ __forceinline__ void upk2(u64 v, float& a, float& b) {
    asm("mov.b64 {%0, %1}, %2;" : "=f"(a), "=f"(b) : "l"(v));
}
__device__ __forceinline__ u64 fma2_(u64 a, u64 b, u64 c) {
    u64 d;
    asm("fma.rn.f32x2 %0, %1, %2, %3;" : "=l"(d) : "l"(a), "l"(b), "l"(c));
    return d;
}
__device__ __forceinline__ u64 mul2_(u64 a, u64 b) {
    u64 d;
    asm("mul.rn.f32x2 %0, %1, %2;" : "=l"(d) : "l"(a), "l"(b));
    return d;
}
__device__ __forceinline__ float ex2f(float x) {
    float y; asm("ex2.approx.f32 %0, %1;" : "=f"(y) : "f"(x)); return y;
}
__device__ __forceinline__ float lg2f(float x) {
    float y; asm("lg2.approx.f32 %0, %1;" : "=f"(y) : "f"(x)); return y;
}
__device__ __forceinline__ float rcpf(float x) {
    float y; asm("rcp.approx.f32 %0, %1;" : "=f"(y) : "f"(x)); return y;
}
__device__ __forceinline__ float half_of(u64 v, int h) {
    float a, b; upk2(v, a, b);
    return h ? b : a;
}

// ---------- Single fused kernel ----------
__global__ __launch_bounds__(THREADS, 5) void attn_kernel(
    const float* __restrict__ feat,
    const float* __restrict__ Wm,
    const float* __restrict__ bia,
    const float* __restrict__ abias,
    const float* __restrict__ gamma,
    const float* __restrict__ beta,
    float* __restrict__ outA, float* __restrict__ outW) {
    // Interleaved t-pair tables: [k][j] = (x_j[2k], x_j[2k+1]), j=0..7
    __shared__ ulonglong2 sPD[NPAIR * 4];    // 16 KB  (P pairs; j7 = 0)
    __shared__ ulonglong2 sVD[NPAIR * 4];    // 16 KB  (V pairs; j7 = (1,1)); later: plain P rows
    __shared__ float4 partA[2][64];          // 2 KB   (merge: a0..a3)
    __shared__ float4 partB[2][64];          // 2 KB   (merge: a4..a7)
    __shared__ float  slinv[ROWS_CTA];       // -log2(rowsum)

    const int b    = blockIdx.y;
    const int quad = blockIdx.x;             // 0..3 -> which 128 rows
    const int tid  = threadIdx.x;
    const int lane = tid & 31;
    const int warp = tid >> 5;
    const int pair = warp >> 1;              // 0/1: row group within CTA
    const int th   = warp & 1;               // 0/1: t-half

    // ---- Fused prep/staging: project + scale, write interleaved tables ----
    {
        const float SC = 0.7384116545f;      // sqrt(log2(e)/sqrt(7))
        float wr[7][7], br[7], ar[7];
#pragma unroll
        for (int e = 0; e < 7; e++) {
            br[e] = __ldg(&bia[e]);
            ar[e] = __ldg(&abias[e]);
#pragma unroll
            for (int d = 0; d < 7; d++) wr[e][d] = __ldg(&Wm[e * 7 + d]);
        }
        float* PDf = reinterpret_cast<float*>(sPD);
        float* VDf = reinterpret_cast<float*>(sVD);
#pragma unroll
        for (int i = 0; i < 4; i++) {
            const int r = tid + i * THREADS;             // 0..511
            const float* fp = feat + ((size_t)b * SEQ + r) * 7;
            float f[7];
#pragma unroll
            for (int d = 0; d < 7; d++) f[d] = fp[d] + ar[d];
            float p[7];
#pragma unroll
            for (int e = 0; e < 7; e++) {
                float s = br[e];
#pragma unroll
                for (int d = 0; d < 7; d++) s = fmaf(f[d], wr[e][d], s);
                p[e] = s * SC;
            }
            const int k = r >> 1, h = r & 1;
#pragma unroll
            for (int j = 0; j < 7; j++) {
                PDf[(k * 8 + j) * 2 + h] = p[j];
                VDf[(k * 8 + j) * 2 + h] = f[j];
            }
            PDf[(k * 8 + 7) * 2 + h] = 0.f;
            VDf[(k * 8 + 7) * 2 + h] = 1.0f;             // rowsum slot
        }
    }
    __syncthreads();

    const int rbase = quad * ROWS_CTA;                   // CTA row offset in batch
    const int rloc0 = pair * 64 + lane;                  // local row of slot 0 (s adds 32)

    // Splatted q: q[s][j] = (q_j, q_j)
    u64 q[RPT][7];
#pragma unroll
    for (int s = 0; s < RPT; s++) {
        const int r = rbase + rloc0 + s * 32;
        const int k = r >> 1, h = r & 1;
        const ulonglong2 d0 = sPD[k * 4 + 0];
        const ulonglong2 d1 = sPD[k * 4 + 1];
        const ulonglong2 d2 = sPD[k * 4 + 2];
        const ulonglong2 d3 = sPD[k * 4 + 3];
        float v;
        v = half_of(d0.x, h); q[s][0] = pk2(v, v);
        v = half_of(d0.y, h); q[s][1] = pk2(v, v);
        v = half_of(d1.x, h); q[s][2] = pk2(v, v);
        v = half_of(d1.y, h); q[s][3] = pk2(v, v);
        v = half_of(d2.x, h); q[s][4] = pk2(v, v);
        v = half_of(d2.y, h); q[s][5] = pk2(v, v);
        v = half_of(d3.x, h); q[s][6] = pk2(v, v);
    }

    // ---- Phase A (t-half): two scores per 7-fma2 chain; even/odd-t acc halves ----
    u64 acc[RPT][8];
#pragma unroll
    for (int s = 0; s < RPT; s++)
#pragma unroll
        for (int j = 0; j < 8; j++) acc[s][j] = 0ull;

    const int k0 = th * 128;
#pragma unroll 4
    for (int kk = 0; kk < 128; kk++) {
        const int k = k0 + kk;
        const ulonglong2 p0 = sPD[k * 4 + 0];
        const ulonglong2 p1 = sPD[k * 4 + 1];
        const ulonglong2 p2 = sPD[k * 4 + 2];
        const ulonglong2 p3 = sPD[k * 4 + 3];
        const ulonglong2 v0 = sVD[k * 4 + 0];
        const ulonglong2 v1 = sVD[k * 4 + 1];
        const ulonglong2 v2 = sVD[k * 4 + 2];
        const ulonglong2 v3 = sVD[k * 4 + 3];   // v3.y = (1,1) rowsum slot
#pragma unroll
        for (int s = 0; s < RPT; s++) {
            u64 z2 = mul2_(q[s][0], p0.x);
            z2 = fma2_(q[s][1], p0.y, z2);
            z2 = fma2_(q[s][2], p1.x, z2);
            z2 = fma2_(q[s][3], p1.y, z2);
            z2 = fma2_(q[s][4], p2.x, z2);
            z2 = fma2_(q[s][5], p2.y, z2);
            z2 = fma2_(q[s][6], p3.x, z2);
            float za, zb; upk2(z2, za, zb);     // z[2k], z[2k+1] — complete, no add
            const u64 ee = pk2(ex2f(za), ex2f(zb));
            acc[s][0] = fma2_(ee, v0.x, acc[s][0]);
            acc[s][1] = fma2_(ee, v0.y, acc[s][1]);
            acc[s][2] = fma2_(ee, v1.x, acc[s][2]);
            acc[s][3] = fma2_(ee, v1.y, acc[s][3]);
            acc[s][4] = fma2_(ee, v2.x, acc[s][4]);
            acc[s][5] = fma2_(ee, v2.y, acc[s][5]);
            acc[s][6] = fma2_(ee, v3.x, acc[s][6]);
            acc[s][7] = fma2_(ee, v3.y, acc[s][7]);
        }
    }

    // Combine even/odd halves into scalars.
    float av[RPT][8];
#pragma unroll
    for (int s = 0; s < RPT; s++)
#pragma unroll
        for (int j = 0; j < 8; j++) {
            float lo, hi; upk2(acc[s][j], lo, hi);
            av[s][j] = lo + hi;
        }

    // ---- Merge t-halves: th=1 publishes scalars, th=0 combines + finishes ----
    if (th == 1) {
#pragma unroll
        for (int s = 0; s < RPT; s++) {
            partA[pair][s * 32 + lane] = make_float4(av[s][0], av[s][1], av[s][2], av[s][3]);
            partB[pair][s * 32 + lane] = make_float4(av[s][4], av[s][5], av[s][6], av[s][7]);
        }
    }
    __syncthreads();

    if (th == 0) {
        float g0 = __ldg(&gamma[0]), g1 = __ldg(&gamma[1]), g2 = __ldg(&gamma[2]),
              g3 = __ldg(&gamma[3]), g4 = __ldg(&gamma[4]), g5 = __ldg(&gamma[5]),
              g6 = __ldg(&gamma[6]);
        float b0 = __ldg(&beta[0]), b1 = __ldg(&beta[1]), b2 = __ldg(&beta[2]),
              b3 = __ldg(&beta[3]), b4 = __ldg(&beta[4]), b5 = __ldg(&beta[5]),
              b6 = __ldg(&beta[6]);
#pragma unroll
        for (int s = 0; s < RPT; s++) {
            const float4 pa = partA[pair][s * 32 + lane];
            const float4 pb = partB[pair][s * 32 + lane];
            float a0 = av[s][0] + pa.x, a1 = av[s][1] + pa.y;
            float a2 = av[s][2] + pa.z, a3 = av[s][3] + pa.w;
            float a4 = av[s][4] + pb.x, a5 = av[s][5] + pb.y;
            float a6 = av[s][6] + pb.z;
            const float sum = av[s][7] + pb.w;
            slinv[rloc0 + s * 32] = -lg2f(sum);
            if (outA) {
                float iv = rcpf(sum);
                a0 *= iv; a1 *= iv; a2 *= iv; a3 *= iv; a4 *= iv; a5 *= iv; a6 *= iv;
                float mu = (a0 + a1 + a2 + a3 + a4 + a5 + a6) * (1.0f / 7.0f);
                float e0 = a0 - mu, e1 = a1 - mu, e2 = a2 - mu, e3 = a3 - mu;
                float e4 = a4 - mu, e5 = a5 - mu, e6 = a6 - mu;
                float var = (e0*e0 + e1*e1 + e2*e2 + e3*e3 + e4*e4 + e5*e5 + e6*e6) * (1.0f / 7.0f);
                float rs = rsqrtf(var + 1e-5f);
                float* oa = outA + (size_t)(b * SEQ + rbase + rloc0 + s * 32) * 7;
                oa[0] = e0 * rs * g0 + b0;
                oa[1] = e1 * rs * g1 + b1;
                oa[2] = e2 * rs * g2 + b2;
                oa[3] = e3 * rs * g3 + b3;
                oa[4] = e4 * rs * g4 + b4;
                oa[5] = e5 * rs * g5 + b5;
                oa[6] = e6 * rs * g6 + b6;
            }
        }
    }

    // ---- Rebuild plain P row table into dead VD space (all threads) ----
    {
        float* plainF = reinterpret_cast<float*>(sVD);
#pragma unroll
        for (int i = 0; i < 4; i++) {
            const int r = tid + i * THREADS;
            const int k = r >> 1, h = r & 1;
            const ulonglong2 d0 = sPD[k * 4 + 0];
            const ulonglong2 d1 = sPD[k * 4 + 1];
            const ulonglong2 d2 = sPD[k * 4 + 2];
            const ulonglong2 d3 = sPD[k * 4 + 3];
            float4 lo4, hi4;
            lo4.x = half_of(d0.x, h); lo4.y = half_of(d0.y, h);
            lo4.z = half_of(d1.x, h); lo4.w = half_of(d1.y, h);
            hi4.x = half_of(d2.x, h); hi4.y = half_of(d2.y, h);
            hi4.z = half_of(d3.x, h); hi4.w = 0.f;
            reinterpret_cast<float4*>(plainF)[r * 2 + 0] = lo4;
            reinterpret_cast<float4*>(plainF)[r * 2 + 1] = hi4;
        }
    }
    __syncthreads();   // plain table + slinv ready

    // ---- Phase B: lane owns t-quad, STG.128 coalesced weight stores ----
    if (outW) {
        const ulonglong2* sPu = reinterpret_cast<const ulonglong2*>(sVD);  // plain rows
        const int tb = warp * 128;        // warp's 128 t-columns
        u64 pt[4][4];
#pragma unroll
        for (int j = 0; j < 4; j++) {
            const int t = tb + lane * 4 + j;
            const ulonglong2 ta = sPu[t * 2 + 0];
            const ulonglong2 tc = sPu[t * 2 + 1];
            pt[j][0] = ta.x; pt[j][1] = ta.y; pt[j][2] = tc.x; pt[j][3] = tc.y;
        }
        float* outBase = outW + ((size_t)(b * SEQ + rbase)) * SEQ + tb;

#pragma unroll 2
        for (int r = 0; r < ROWS_CTA; r++) {
            const ulonglong2 rA = sPu[(rbase + r) * 2 + 0];   // uniform loads
            const ulonglong2 rB = sPu[(rbase + r) * 2 + 1];
            const u64 lv2 = pk2(slinv[r], 0.f);
            const u64 r0 = rA.x, r1 = rA.y, r2 = rB.x, r3 = rB.y;  // pad 0
            float4 wv;
            {
                u64 z2 = fma2_(r0, pt[0][0], lv2);
                z2 = fma2_(r1, pt[0][1], z2);
                z2 = fma2_(r2, pt[0][2], z2);
                z2 = fma2_(r3, pt[0][3], z2);
                float za, zb; upk2(z2, za, zb);
                wv.x = ex2f(za + zb);
            }
            {
                u64 z2 = fma2_(r0, pt[1][0], lv2);
                z2 = fma2_(r1, pt[1][1], z2);
                z2 = fma2_(r2, pt[1][2], z2);
                z2 = fma2_(r3, pt[1][3], z2);
                float za, zb; upk2(z2, za, zb);
                wv.y = ex2f(za + zb);
            }
            {
                u64 z2 = fma2_(r0, pt[2][0], lv2);
                z2 = fma2_(r1, pt[2][1], z2);
                z2 = fma2_(r2, pt[2][2], z2);
                z2 = fma2_(r3, pt[2][3], z2);
                float za, zb; upk2(z2, za, zb);
                wv.z = ex2f(za + zb);
            }
            {
                u64 z2 = fma2_(r0, pt[3][0], lv2);
                z2 = fma2_(r1, pt[3][1], z2);
                z2 = fma2_(r2, pt[3][2], z2);
                z2 = fma2_(r3, pt[3][3], z2);
                float za, zb; upk2(z2, za, zb);
                wv.w = ex2f(za + zb);
            }
            *reinterpret_cast<float4*>(outBase + (size_t)r * SEQ + lane * 4) = wv;
        }
    }
}

extern "C" void kernel_launch(void* const* d_in, const int* in_sizes, int n_in,
                              void* d_out, int out_size) {
    const float* features = (const float*)d_in[0];
    const float* W        = (const float*)d_in[1];
    const float* bias     = (const float*)d_in[2];
    const float* abias    = (const float*)d_in[3];
    const float* gamma    = (const float*)d_in[4];
    const float* beta     = (const float*)d_in[5];

    float* out = (float*)d_out;
    const long long nA = (long long)BATCH * SEQ * DIM;       // 917504
    const long long nW = (long long)BATCH * SEQ * SEQ;       // 67108864
    float* outA = nullptr;
    float* outW = nullptr;
    long long total = (long long)out_size;
    if (total == nA + nW)      { outA = out; outW = out + nA; }
    else if (total == nW)      { outW = out; }
    else if (total == nA)      { outA = out; }
    else                       { outA = out; outW = out + nA; }

    attn_kernel<<<dim3(4, BATCH), THREADS>>>(features, W, bias, abias,
                                             gamma, beta, outA, outW);
}